// round 2
// baseline (speedup 1.0000x reference)
#include <cuda_runtime.h>
#include <math.h>
#include <stdint.h>

#define LNUM 2
#define IN_DIM 172
#define HID 128
#define NH 4
#define HD 32
#define TD 100
#define NMAX 150016
#define EMAX 500224
#define BMAX 16384

#define ID_H    0
#define ID_Q    1
#define ID_K    2
#define ID_V    3
#define ID_OUT  4
#define ID_Z1   5
#define ID_Z2   6
#define ID_S    7
#define ID_SUMS 8

// ---------------- scratch (static device memory; no cudaMalloc allowed) ----------------
__device__ float  g_h  [(size_t)NMAX * HID];
__device__ float  g_q  [(size_t)NMAX * HID];
__device__ float  g_k  [(size_t)NMAX * HID];
__device__ float  g_v  [(size_t)NMAX * HID];
__device__ float  g_out[(size_t)NMAX * HID];
__device__ float  g_e  [(size_t)EMAX * HID];   // holds v[src] + e  per edge
__device__ float  g_a  [(size_t)EMAX * NH];
__device__ float  g_s  [(size_t)NMAX * NH];
__device__ float  g_z1 [(size_t)BMAX * HID];
__device__ float  g_z2 [(size_t)BMAX * (HID/2)];
__device__ double g_sums[256];   // [0:128) col sums, [128:256) col sumsq
__device__ float  g_bnp[256];    // [0:128) mul, [128:256) add

__device__ __forceinline__ float* bufptr(int id) {
    switch (id) {
        case ID_H:    return g_h;
        case ID_Q:    return g_q;
        case ID_K:    return g_k;
        case ID_V:    return g_v;
        case ID_OUT:  return g_out;
        case ID_Z1:   return g_z1;
        case ID_Z2:   return g_z2;
        case ID_S:    return g_s;
        case ID_SUMS: return (float*)g_sums;
    }
    return nullptr;
}

// ---------------- generic tiled GEMM: C[M,NC] = op(A)[M,K] @ W[K,NC] + bias ----------------
template <int NC>
__global__ void gemm_kernel(const float* __restrict__ Aext, int Aid,
                            const int* __restrict__ gather,
                            int M, int K,
                            const float* __restrict__ W,
                            const float* __restrict__ bias,
                            int Cid, int relu)
{
    constexpr int BM = 64, BK = 32;
    constexpr int TX = NC / 4;        // 32 (NC=128) or 16 (NC=64)
    constexpr int TY = 256 / TX;      // 8 or 16
    constexpr int RT = BM / TY;       // 8 or 4
    __shared__ float As[BM * BK];     // row-major [r][kk]
    __shared__ float Ws[BK * NC];     // row-major [kk][c]

    const float* A = (Aid >= 0) ? bufptr(Aid) : Aext;
    float* C = bufptr(Cid);

    int row0 = blockIdx.x * BM;
    int tx = threadIdx.x % TX;
    int ty = threadIdx.x / TX;

    float acc[RT][4];
    #pragma unroll
    for (int r = 0; r < RT; r++) { acc[r][0]=0.f; acc[r][1]=0.f; acc[r][2]=0.f; acc[r][3]=0.f; }

    for (int k0 = 0; k0 < K; k0 += BK) {
        for (int idx = threadIdx.x; idx < BM * BK; idx += 256) {
            int r = idx / BK, kk = idx % BK;
            int row = row0 + r;
            float v = 0.f;
            if (row < M && (k0 + kk) < K) {
                int ar = gather ? gather[row] : row;
                v = A[(size_t)ar * K + k0 + kk];
            }
            As[idx] = v;
        }
        for (int idx = threadIdx.x; idx < BK * NC; idx += 256) {
            int kk = idx / NC;
            Ws[idx] = ((k0 + kk) < K) ? W[(size_t)(k0 + kk) * NC + (idx % NC)] : 0.f;
        }
        __syncthreads();

        #pragma unroll
        for (int kk4 = 0; kk4 < BK / 4; kk4++) {
            float4 w0 = ((const float4*)Ws)[(kk4*4 + 0) * TX + tx];
            float4 w1 = ((const float4*)Ws)[(kk4*4 + 1) * TX + tx];
            float4 w2 = ((const float4*)Ws)[(kk4*4 + 2) * TX + tx];
            float4 w3 = ((const float4*)Ws)[(kk4*4 + 3) * TX + tx];
            #pragma unroll
            for (int r = 0; r < RT; r++) {
                float4 a = ((const float4*)As)[(ty * RT + r) * (BK/4) + kk4];
                acc[r][0] += a.x*w0.x + a.y*w1.x + a.z*w2.x + a.w*w3.x;
                acc[r][1] += a.x*w0.y + a.y*w1.y + a.z*w2.y + a.w*w3.y;
                acc[r][2] += a.x*w0.z + a.y*w1.z + a.z*w2.z + a.w*w3.z;
                acc[r][3] += a.x*w0.w + a.y*w1.w + a.z*w2.w + a.w*w3.w;
            }
        }
        __syncthreads();
    }

    float4 b4 = ((const float4*)bias)[tx];
    #pragma unroll
    for (int r = 0; r < RT; r++) {
        int row = row0 + ty * RT + r;
        if (row < M) {
            float4 o;
            o.x = acc[r][0] + b4.x; o.y = acc[r][1] + b4.y;
            o.z = acc[r][2] + b4.z; o.w = acc[r][3] + b4.w;
            if (relu) {
                o.x = fmaxf(o.x, 0.f); o.y = fmaxf(o.y, 0.f);
                o.z = fmaxf(o.z, 0.f); o.w = fmaxf(o.w, 0.f);
            }
            ((float4*)C)[(size_t)row * (NC/4) + tx] = o;
        }
    }
}

// ---------------- edge pass A ----------------
// te = cos(dt*f+p); e = te@We; alpha = q[dst].(k[src]+e)/sqrt(HD); a=exp(alpha);
// s[dst] += a; g_e[e] = v[src] + e   (pre-adding v so pass B needs no src gather)
__global__ void edgeA_kernel(const int* __restrict__ src, const int* __restrict__ dst,
                             const float* __restrict__ dt,
                             const float* __restrict__ freq, const float* __restrict__ ph,
                             const float* __restrict__ We, int E)
{
    extern __shared__ float sh[];
    float* Wes = sh;                 // TD*HID
    float* tes = sh + TD * HID;      // 8 warps * 4 edges * TD (interleaved [t*4+j])

    for (int idx = threadIdx.x; idx < TD * HID; idx += blockDim.x) Wes[idx] = We[idx];
    __syncthreads();

    int warp = threadIdx.x >> 5, lane = threadIdx.x & 31;
    float* myte = tes + warp * (4 * TD);
    const float4* W4 = (const float4*)Wes;
    const float inv_sqrt_d = 0.1767766952966369f;

    long long base = (long long)blockIdx.x * 128 + warp * 16;

    for (int it = 0; it < 4; it++) {
        long long e0 = base + it * 4;
        float d[4];
        #pragma unroll
        for (int j = 0; j < 4; j++) {
            long long e = e0 + j;
            d[j] = (e < E) ? dt[e] : 0.f;
        }
        for (int t = lane; t < TD; t += 32) {
            float f = freq[t], p = ph[t];
            float4 tv;
            tv.x = cosf(fmaf(d[0], f, p));
            tv.y = cosf(fmaf(d[1], f, p));
            tv.z = cosf(fmaf(d[2], f, p));
            tv.w = cosf(fmaf(d[3], f, p));
            ((float4*)myte)[t] = tv;
        }
        __syncwarp();

        float4 accs[4];
        #pragma unroll
        for (int j = 0; j < 4; j++) { accs[j].x=0.f; accs[j].y=0.f; accs[j].z=0.f; accs[j].w=0.f; }

        #pragma unroll 4
        for (int t = 0; t < TD; t++) {
            float4 tv = ((const float4*)myte)[t];
            float4 w  = W4[t * 32 + lane];
            accs[0].x += tv.x*w.x; accs[0].y += tv.x*w.y; accs[0].z += tv.x*w.z; accs[0].w += tv.x*w.w;
            accs[1].x += tv.y*w.x; accs[1].y += tv.y*w.y; accs[1].z += tv.y*w.z; accs[1].w += tv.y*w.w;
            accs[2].x += tv.z*w.x; accs[2].y += tv.z*w.y; accs[2].z += tv.z*w.z; accs[2].w += tv.z*w.w;
            accs[3].x += tv.w*w.x; accs[3].y += tv.w*w.y; accs[3].z += tv.w*w.z; accs[3].w += tv.w*w.w;
        }

        #pragma unroll
        for (int j = 0; j < 4; j++) {
            long long e = e0 + j;
            if (e >= E) continue;
            float4 ev = accs[j];
            int sI = src[e], dI = dst[e];
            float4 kv = ((const float4*)g_k)[(size_t)sI * 32 + lane];
            float4 qv = ((const float4*)g_q)[(size_t)dI * 32 + lane];
            float4 vv = ((const float4*)g_v)[(size_t)sI * 32 + lane];
            float4 ve; ve.x = vv.x + ev.x; ve.y = vv.y + ev.y; ve.z = vv.z + ev.z; ve.w = vv.w + ev.w;
            ((float4*)g_e)[(size_t)e * 32 + lane] = ve;
            float p = qv.x*(kv.x+ev.x) + qv.y*(kv.y+ev.y) + qv.z*(kv.z+ev.z) + qv.w*(kv.w+ev.w);
            p += __shfl_xor_sync(0xffffffffu, p, 1);
            p += __shfl_xor_sync(0xffffffffu, p, 2);
            p += __shfl_xor_sync(0xffffffffu, p, 4);
            if ((lane & 7) == 0) {
                int head = lane >> 3;
                float a = expf(p * inv_sqrt_d);
                g_a[(size_t)e * NH + head] = a;
                atomicAdd(&g_s[(size_t)dI * NH + head], a);
            }
        }
        __syncwarp();
    }
}

// ---------------- edge pass B: out[dst] += (a/s[dst]) * g_e[e] ----------------
__global__ void edgeB_kernel(const int* __restrict__ dst, int E)
{
    long long e = (long long)blockIdx.x * 8 + (threadIdx.x >> 5);
    if (e >= E) return;
    int lane = threadIdx.x & 31;
    int dI = dst[e];
    int head = lane >> 3;
    float a = g_a[(size_t)e * NH + head];
    float ssum = g_s[(size_t)dI * NH + head];
    float w = a / (ssum + 1e-16f);
    float4 ve = ((const float4*)g_e)[(size_t)e * 32 + lane];
    float4 contrib;
    contrib.x = w * ve.x; contrib.y = w * ve.y; contrib.z = w * ve.z; contrib.w = w * ve.w;
#if __CUDA_ARCH__ >= 900
    atomicAdd(((float4*)g_out) + (size_t)dI * 32 + lane, contrib);
#else
    float* o = g_out + (size_t)dI * HID + lane * 4;
    atomicAdd(o + 0, contrib.x);
    atomicAdd(o + 1, contrib.y);
    atomicAdd(o + 2, contrib.z);
    atomicAdd(o + 3, contrib.w);
#endif
}

// ---------------- utility kernels ----------------
__global__ void zero_kernel(int id, int n)
{
    float* p = bufptr(id);
    for (int i = blockIdx.x * blockDim.x + threadIdx.x; i < n; i += gridDim.x * blockDim.x)
        p[i] = 0.f;
}

__global__ void stats_kernel(int id, int n, int ncols, int prerelu)
{
    const float* X = bufptr(id);
    int c = threadIdx.x;
    float s = 0.f, s2 = 0.f;
    for (int r = blockIdx.x; r < n; r += gridDim.x) {
        float v = X[(size_t)r * ncols + c];
        if (prerelu) v = fmaxf(v, 0.f);
        s += v; s2 += v * v;
    }
    atomicAdd(&g_sums[c], (double)s);
    atomicAdd(&g_sums[128 + c], (double)s2);
}

__global__ void bnfin_kernel(int n, const float* __restrict__ gamma, const float* __restrict__ beta)
{
    int c = threadIdx.x;
    double mean = g_sums[c] / (double)n;
    double var  = g_sums[128 + c] / (double)n - mean * mean;
    float mul = gamma[c] * rsqrtf((float)var + 1e-5f);
    g_bnp[c] = mul;
    g_bnp[128 + c] = beta[c] - (float)mean * mul;
}

__global__ void bn_kernel(int inid, int outid, int n, int ncols, int prerelu, int postrelu)
{
    const float* X = bufptr(inid);
    float* Y = bufptr(outid);
    size_t total = (size_t)n * ncols;
    for (size_t i = (size_t)blockIdx.x * blockDim.x + threadIdx.x; i < total;
         i += (size_t)gridDim.x * blockDim.x) {
        int c = (int)(i % ncols);
        float v = X[i];
        if (prerelu) v = fmaxf(v, 0.f);
        float y = v * g_bnp[c] + g_bnp[128 + c];
        if (postrelu) y = fmaxf(y, 0.f);
        Y[i] = y;
    }
}

// final: out[r] = z2[r,:] . W3 + b3   (warp per row)
__global__ void final_kernel(const float* __restrict__ W3, const float* __restrict__ b3,
                             float* __restrict__ out, int B)
{
    int r = (blockIdx.x * blockDim.x + threadIdx.x) >> 5;
    int lane = threadIdx.x & 31;
    if (r >= B) return;
    const float* z = g_z2 + (size_t)r * 64;
    float acc = z[lane] * W3[lane] + z[lane + 32] * W3[lane + 32];
    acc += __shfl_xor_sync(0xffffffffu, acc, 1);
    acc += __shfl_xor_sync(0xffffffffu, acc, 2);
    acc += __shfl_xor_sync(0xffffffffu, acc, 4);
    acc += __shfl_xor_sync(0xffffffffu, acc, 8);
    acc += __shfl_xor_sync(0xffffffffu, acc, 16);
    if (lane == 0) out[r] = acc + b3[0];
}

// ---------------- host launcher ----------------
extern "C" void kernel_launch(void* const* d_in, const int* in_sizes, int n_in,
                              void* d_out, int out_size)
{
    int off = (n_in >= 31) ? 1 : 0;   // batch_size scalar may or may not be materialized
    const float* x_all = (const float*)d_in[0];
    const int*   ids   = (const int*)d_in[1];
    const int*   esrc  = (const int*)d_in[2];
    const int*   edst  = (const int*)d_in[3];
    const float* dts   = (const float*)d_in[4];
    const float* basis = (const float*)d_in[5 + off];
    const float* phase = (const float*)d_in[6 + off];
    const float* Wp    = (const float*)d_in[7 + off];
    const float* bp    = (const float*)d_in[8 + off];
    const float* Wq    = (const float*)d_in[9 + off];
    const float* bq    = (const float*)d_in[10 + off];
    const float* Wk    = (const float*)d_in[11 + off];
    const float* bk    = (const float*)d_in[12 + off];
    const float* Wv    = (const float*)d_in[13 + off];
    const float* bv    = (const float*)d_in[14 + off];
    const float* We    = (const float*)d_in[15 + off];
    const float* Wsk   = (const float*)d_in[16 + off];
    const float* bsk   = (const float*)d_in[17 + off];
    const float* bng   = (const float*)d_in[18 + off];
    const float* bnb   = (const float*)d_in[19 + off];
    const float* W1    = (const float*)d_in[20 + off];
    const float* b1    = (const float*)d_in[21 + off];
    const float* g1    = (const float*)d_in[22 + off];
    const float* be1   = (const float*)d_in[23 + off];
    const float* W2    = (const float*)d_in[24 + off];
    const float* b2    = (const float*)d_in[25 + off];
    const float* g2    = (const float*)d_in[26 + off];
    const float* be2   = (const float*)d_in[27 + off];
    const float* W3    = (const float*)d_in[28 + off];
    const float* b3    = (const float*)d_in[29 + off];

    int N = in_sizes[1];
    int E = in_sizes[2] / LNUM;
    int B = out_size;

    int gN = (N + 63) / 64;
    int gB = (B + 63) / 64;

    const int EDGEA_SMEM = (TD * HID + 8 * 4 * TD) * (int)sizeof(float);  // 64000 B
    cudaFuncSetAttribute(edgeA_kernel, cudaFuncAttributeMaxDynamicSharedMemorySize, EDGEA_SMEM);

    // h = relu(x_all[ids] @ Wp + bp)
    gemm_kernel<128><<<gN, 256>>>(x_all, -1, ids, N, IN_DIM, Wp, bp, ID_H, 1);

    for (int i = 0; i < LNUM; i++) {
        size_t wo = (size_t)i * HID * HID;
        gemm_kernel<128><<<gN, 256>>>(nullptr, ID_H, nullptr, N, HID, Wq + wo, bq + i*HID, ID_Q, 0);
        gemm_kernel<128><<<gN, 256>>>(nullptr, ID_H, nullptr, N, HID, Wk + wo, bk + i*HID, ID_K, 0);
        gemm_kernel<128><<<gN, 256>>>(nullptr, ID_H, nullptr, N, HID, Wv + wo, bv + i*HID, ID_V, 0);
        gemm_kernel<128><<<gN, 256>>>(nullptr, ID_H, nullptr, N, HID, Wsk + wo, bsk + i*HID, ID_OUT, 0);

        zero_kernel<<<256, 256>>>(ID_S, N * NH);
        edgeA_kernel<<<(E + 127) / 128, 256, EDGEA_SMEM>>>(
            esrc + (size_t)i * E, edst + (size_t)i * E, dts + (size_t)i * E,
            basis, phase, We + (size_t)i * TD * HID, E);
        edgeB_kernel<<<(E + 7) / 8, 256>>>(edst + (size_t)i * E, E);

        zero_kernel<<<4, 256>>>(ID_SUMS, 512);
        stats_kernel<<<512, HID>>>(ID_OUT, N, HID, 1);
        bnfin_kernel<<<1, HID>>>(N, bng + i*HID, bnb + i*HID);
        bn_kernel<<<2048, 256>>>(ID_OUT, ID_H, N, HID, 1, 0);
    }

    // MLP head on first B rows
    gemm_kernel<128><<<gB, 256>>>(nullptr, ID_H, nullptr, B, HID, W1, b1, ID_Z1, 0);
    zero_kernel<<<4, 256>>>(ID_SUMS, 512);
    stats_kernel<<<512, 128>>>(ID_Z1, B, 128, 0);
    bnfin_kernel<<<1, 128>>>(B, g1, be1);
    bn_kernel<<<1024, 256>>>(ID_Z1, ID_Z1, B, 128, 0, 1);

    gemm_kernel<64><<<gB, 256>>>(nullptr, ID_Z1, nullptr, B, HID, W2, b2, ID_Z2, 0);
    zero_kernel<<<4, 256>>>(ID_SUMS, 512);
    stats_kernel<<<512, 64>>>(ID_Z2, B, 64, 0);
    bnfin_kernel<<<1, 64>>>(B, g2, be2);
    bn_kernel<<<1024, 256>>>(ID_Z2, ID_Z2, B, 64, 0, 1);

    final_kernel<<<(B * 32 + 255) / 256, 256>>>(W3, b3, (float*)d_out, B);
}

// round 4
// speedup vs baseline: 1.1187x; 1.1187x over previous
#include <cuda_runtime.h>
#include <cuda_bf16.h>
#include <math.h>
#include <stdint.h>

#define LNUM 2
#define IN_DIM 172
#define HID 128
#define NH 4
#define HD 32
#define TD 100
#define NMAX 150016
#define EMAX 500224
#define BMAX 16384

#define ID_H    0
#define ID_Q    1
#define ID_K    2
#define ID_V    3
#define ID_OUT  4
#define ID_Z1   5
#define ID_Z2   6
#define ID_S    7
#define ID_SUMS 8

// ---------------- scratch (static device memory; no cudaMalloc allowed) ----------------
__device__ float  g_h  [(size_t)NMAX * HID];
__device__ float  g_q  [(size_t)NMAX * HID];
__device__ float  g_k  [(size_t)NMAX * HID];
__device__ float  g_v  [(size_t)NMAX * HID];
__device__ float  g_out[(size_t)NMAX * HID];
__device__ float  g_e  [(size_t)EMAX * HID];   // holds v[src] + e  per edge
__device__ float  g_a  [(size_t)EMAX * NH];
__device__ float  g_s  [(size_t)NMAX * NH];
__device__ float  g_z1 [(size_t)BMAX * HID];
__device__ float  g_z2 [(size_t)BMAX * (HID/2)];
__device__ double g_sums[256];   // [0:128) col sums, [128:256) col sumsq
__device__ float  g_bnp[256];    // [0:128) mul, [128:256) add

__device__ __forceinline__ float* bufptr(int id) {
    switch (id) {
        case ID_H:    return g_h;
        case ID_Q:    return g_q;
        case ID_K:    return g_k;
        case ID_V:    return g_v;
        case ID_OUT:  return g_out;
        case ID_Z1:   return g_z1;
        case ID_Z2:   return g_z2;
        case ID_S:    return g_s;
        case ID_SUMS: return (float*)g_sums;
    }
    return nullptr;
}

// ---------------- bf16 hi/lo split helpers ----------------
__device__ __forceinline__ void bsplit(float x, float y, uint32_t& hi, uint32_t& lo) {
    __nv_bfloat162 h = __floats2bfloat162_rn(x, y);   // .x = x (low 16 bits)
    hi = *reinterpret_cast<uint32_t*>(&h);
    float rx = x - __bfloat162float(h.x);
    float ry = y - __bfloat162float(h.y);
    __nv_bfloat162 l = __floats2bfloat162_rn(rx, ry);
    lo = *reinterpret_cast<uint32_t*>(&l);
}

__device__ __forceinline__ void mma_bf16(float* c, const uint32_t* a, const uint32_t* b) {
    asm volatile(
        "mma.sync.aligned.m16n8k16.row.col.f32.bf16.bf16.f32 "
        "{%0,%1,%2,%3}, {%4,%5,%6,%7}, {%8,%9}, {%0,%1,%2,%3};\n"
        : "+f"(c[0]), "+f"(c[1]), "+f"(c[2]), "+f"(c[3])
        : "r"(a[0]), "r"(a[1]), "r"(a[2]), "r"(a[3]), "r"(b[0]), "r"(b[1]));
}

// ---------------- tensor-core GEMM: C[M,NC] = gather(A)[M,K] @ W[K,NC] + bias ----------------
// bf16 hi/lo split, 3 MMA products (hh + hl + lh) => ~fp32 accuracy (err ~1.5e-5).
// Block: 128 rows x NC cols, BK=32, 8 warps (4m x 2n), warp tile 32 x (NC/2).
template <int NC>
__global__ void __launch_bounds__(256)
gemm_tc(const float* __restrict__ Aext, int Aid, const int* __restrict__ gather,
        int M, int K, const float* __restrict__ W, const float* __restrict__ bias,
        int Cid, int relu)
{
    constexpr int BM = 128, BK = 32, K2 = 16;
    constexpr int AP = 20;        // uint32 columns per A smem row (16 + 4 pad) -> conflict-free
    constexpr int WP = NC + 8;    // W smem row pad -> conflict-free
    constexpr int WN = NC / 2;    // per-warp n extent (64 or 32)
    constexpr int NT = WN / 8;    // 8 or 4
    constexpr int MT = 2;

    __shared__ uint32_t Ah[BM][AP], Al[BM][AP];   // packed bf16 pairs along k
    __shared__ uint32_t Wh[K2][WP], Wl[K2][WP];

    const float* A = (Aid >= 0) ? bufptr(Aid) : Aext;
    float* C = bufptr(Cid);

    const int tid  = threadIdx.x;
    const int warp = tid >> 5, lane = tid & 31;
    const int wm = warp >> 1, wn = warp & 1;      // 4 x 2 warp grid
    const int lr = lane >> 2, lc = lane & 3;
    const int row0 = blockIdx.x * BM;

    float acc[MT][NT][4];
    #pragma unroll
    for (int mt = 0; mt < MT; mt++)
        #pragma unroll
        for (int nt = 0; nt < NT; nt++)
            #pragma unroll
            for (int j = 0; j < 4; j++) acc[mt][nt][j] = 0.f;

    for (int k0 = 0; k0 < K; k0 += BK) {
        // ---- fill A tile (coalesced float4 reads, uint2 packed stores) ----
        #pragma unroll
        for (int i = 0; i < 4; i++) {
            int task = tid + i * 256;       // 1024 tasks = 128 rows x 8 float4-groups
            int r  = task >> 3;
            int kg = task & 7;
            int k  = k0 + kg * 4;
            float4 v = make_float4(0.f, 0.f, 0.f, 0.f);
            int grow = row0 + r;
            if (grow < M) {
                long long ar = gather ? (long long)gather[grow] : (long long)grow;
                const float* ap = A + ar * K + k;
                if (k + 4 <= K) v = *(const float4*)ap;
                else {
                    if (k     < K) v.x = ap[0];
                    if (k + 1 < K) v.y = ap[1];
                    if (k + 2 < K) v.z = ap[2];
                    if (k + 3 < K) v.w = ap[3];
                }
            }
            uint32_t h0, l0, h1, l1;
            bsplit(v.x, v.y, h0, l0);
            bsplit(v.z, v.w, h1, l1);
            *(uint2*)&Ah[r][kg * 2] = make_uint2(h0, h1);
            *(uint2*)&Al[r][kg * 2] = make_uint2(l0, l1);
        }
        // ---- fill W tile (coalesced float4 reads, uint4 stores) ----
        #pragma unroll
        for (int i = 0; i < (K2 * NC / 4) / 256; i++) {
            int task = tid + i * 256;       // K2 x NC/4 tasks
            int kk = task / (NC / 4);
            int n  = (task % (NC / 4)) * 4;
            int k  = k0 + kk * 2;
            float4 r0 = make_float4(0.f,0.f,0.f,0.f), r1 = make_float4(0.f,0.f,0.f,0.f);
            if (k     < K) r0 = *(const float4*)(W + (size_t)k * NC + n);
            if (k + 1 < K) r1 = *(const float4*)(W + (size_t)(k + 1) * NC + n);
            uint4 vh, vl;
            bsplit(r0.x, r1.x, vh.x, vl.x);
            bsplit(r0.y, r1.y, vh.y, vl.y);
            bsplit(r0.z, r1.z, vh.z, vl.z);
            bsplit(r0.w, r1.w, vh.w, vl.w);
            *(uint4*)&Wh[kk][n] = vh;
            *(uint4*)&Wl[kk][n] = vl;
        }
        __syncthreads();

        #pragma unroll
        for (int ks = 0; ks < 2; ks++) {
            const int kb = ks * 8;
            uint32_t ah[MT][4], al[MT][4], bh[NT][2], bl[NT][2];
            #pragma unroll
            for (int mt = 0; mt < MT; mt++) {
                int m = wm * 32 + mt * 16 + lr;
                ah[mt][0] = Ah[m    ][kb + lc];
                ah[mt][1] = Ah[m + 8][kb + lc];
                ah[mt][2] = Ah[m    ][kb + lc + 4];
                ah[mt][3] = Ah[m + 8][kb + lc + 4];
                al[mt][0] = Al[m    ][kb + lc];
                al[mt][1] = Al[m + 8][kb + lc];
                al[mt][2] = Al[m    ][kb + lc + 4];
                al[mt][3] = Al[m + 8][kb + lc + 4];
            }
            #pragma unroll
            for (int nt = 0; nt < NT; nt++) {
                int n = wn * WN + nt * 8 + lr;
                bh[nt][0] = Wh[kb + lc    ][n];
                bh[nt][1] = Wh[kb + lc + 4][n];
                bl[nt][0] = Wl[kb + lc    ][n];
                bl[nt][1] = Wl[kb + lc + 4][n];
            }
            #pragma unroll
            for (int mt = 0; mt < MT; mt++)
                #pragma unroll
                for (int nt = 0; nt < NT; nt++)
                    mma_bf16(acc[mt][nt], ah[mt], bh[nt]);
            #pragma unroll
            for (int mt = 0; mt < MT; mt++)
                #pragma unroll
                for (int nt = 0; nt < NT; nt++)
                    mma_bf16(acc[mt][nt], ah[mt], bl[nt]);
            #pragma unroll
            for (int mt = 0; mt < MT; mt++)
                #pragma unroll
                for (int nt = 0; nt < NT; nt++)
                    mma_bf16(acc[mt][nt], al[mt], bh[nt]);
        }
        __syncthreads();
    }

    // ---- epilogue: bias (+relu), float2 stores ----
    #pragma unroll
    for (int mt = 0; mt < MT; mt++) {
        int rA = row0 + wm * 32 + mt * 16 + lr;
        #pragma unroll
        for (int nt = 0; nt < NT; nt++) {
            int col = wn * WN + nt * 8 + lc * 2;
            float b0 = bias[col], b1 = bias[col + 1];
            float2 v0 = make_float2(acc[mt][nt][0] + b0, acc[mt][nt][1] + b1);
            float2 v1 = make_float2(acc[mt][nt][2] + b0, acc[mt][nt][3] + b1);
            if (relu) {
                v0.x = fmaxf(v0.x, 0.f); v0.y = fmaxf(v0.y, 0.f);
                v1.x = fmaxf(v1.x, 0.f); v1.y = fmaxf(v1.y, 0.f);
            }
            if (rA     < M) *(float2*)&C[(size_t)rA * NC + col]       = v0;
            if (rA + 8 < M) *(float2*)&C[(size_t)(rA + 8) * NC + col] = v1;
        }
    }
}

// ---------------- edge pass A ----------------
// te = cos(dt*f+p); e = te@We; alpha = q[dst].(k[src]+e)/sqrt(HD); a=exp(alpha);
// s[dst] += a; g_e[e] = v[src] + e   (pre-adding v so pass B needs no src gather)
__global__ void edgeA_kernel(const int* __restrict__ src, const int* __restrict__ dst,
                             const float* __restrict__ dt,
                             const float* __restrict__ freq, const float* __restrict__ ph,
                             const float* __restrict__ We, int E)
{
    extern __shared__ float sh[];
    float* Wes = sh;                 // TD*HID
    float* tes = sh + TD * HID;      // 8 warps * 4 edges * TD (interleaved [t*4+j])

    for (int idx = threadIdx.x; idx < TD * HID; idx += blockDim.x) Wes[idx] = We[idx];
    __syncthreads();

    int warp = threadIdx.x >> 5, lane = threadIdx.x & 31;
    float* myte = tes + warp * (4 * TD);
    const float4* W4 = (const float4*)Wes;
    const float inv_sqrt_d = 0.1767766952966369f;

    long long base = (long long)blockIdx.x * 128 + warp * 16;

    for (int it = 0; it < 4; it++) {
        long long e0 = base + it * 4;
        float d[4];
        #pragma unroll
        for (int j = 0; j < 4; j++) {
            long long e = e0 + j;
            d[j] = (e < E) ? dt[e] : 0.f;
        }
        for (int t = lane; t < TD; t += 32) {
            float f = freq[t], p = ph[t];
            float4 tv;
            tv.x = cosf(fmaf(d[0], f, p));
            tv.y = cosf(fmaf(d[1], f, p));
            tv.z = cosf(fmaf(d[2], f, p));
            tv.w = cosf(fmaf(d[3], f, p));
            ((float4*)myte)[t] = tv;
        }
        __syncwarp();

        float4 accs[4];
        #pragma unroll
        for (int j = 0; j < 4; j++) { accs[j].x=0.f; accs[j].y=0.f; accs[j].z=0.f; accs[j].w=0.f; }

        #pragma unroll 4
        for (int t = 0; t < TD; t++) {
            float4 tv = ((const float4*)myte)[t];
            float4 w  = W4[t * 32 + lane];
            accs[0].x += tv.x*w.x; accs[0].y += tv.x*w.y; accs[0].z += tv.x*w.z; accs[0].w += tv.x*w.w;
            accs[1].x += tv.y*w.x; accs[1].y += tv.y*w.y; accs[1].z += tv.y*w.z; accs[1].w += tv.y*w.w;
            accs[2].x += tv.z*w.x; accs[2].y += tv.z*w.y; accs[2].z += tv.z*w.z; accs[2].w += tv.z*w.w;
            accs[3].x += tv.w*w.x; accs[3].y += tv.w*w.y; accs[3].z += tv.w*w.z; accs[3].w += tv.w*w.w;
        }

        #pragma unroll
        for (int j = 0; j < 4; j++) {
            long long e = e0 + j;
            if (e >= E) continue;
            float4 ev = accs[j];
            int sI = src[e], dI = dst[e];
            float4 kv = ((const float4*)g_k)[(size_t)sI * 32 + lane];
            float4 qv = ((const float4*)g_q)[(size_t)dI * 32 + lane];
            float4 vv = ((const float4*)g_v)[(size_t)sI * 32 + lane];
            float4 ve; ve.x = vv.x + ev.x; ve.y = vv.y + ev.y; ve.z = vv.z + ev.z; ve.w = vv.w + ev.w;
            ((float4*)g_e)[(size_t)e * 32 + lane] = ve;
            float p = qv.x*(kv.x+ev.x) + qv.y*(kv.y+ev.y) + qv.z*(kv.z+ev.z) + qv.w*(kv.w+ev.w);
            p += __shfl_xor_sync(0xffffffffu, p, 1);
            p += __shfl_xor_sync(0xffffffffu, p, 2);
            p += __shfl_xor_sync(0xffffffffu, p, 4);
            if ((lane & 7) == 0) {
                int head = lane >> 3;
                float a = expf(p * inv_sqrt_d);
                g_a[(size_t)e * NH + head] = a;
                atomicAdd(&g_s[(size_t)dI * NH + head], a);
            }
        }
        __syncwarp();
    }
}

// ---------------- edge pass B: out[dst] += (a/s[dst]) * g_e[e] ----------------
__global__ void edgeB_kernel(const int* __restrict__ dst, int E)
{
    long long e = (long long)blockIdx.x * 8 + (threadIdx.x >> 5);
    if (e >= E) return;
    int lane = threadIdx.x & 31;
    int dI = dst[e];
    int head = lane >> 3;
    float a = g_a[(size_t)e * NH + head];
    float ssum = g_s[(size_t)dI * NH + head];
    float w = a / (ssum + 1e-16f);
    float4 ve = ((const float4*)g_e)[(size_t)e * 32 + lane];
    float4 contrib;
    contrib.x = w * ve.x; contrib.y = w * ve.y; contrib.z = w * ve.z; contrib.w = w * ve.w;
#if __CUDA_ARCH__ >= 900
    atomicAdd(((float4*)g_out) + (size_t)dI * 32 + lane, contrib);
#else
    float* o = g_out + (size_t)dI * HID + lane * 4;
    atomicAdd(o + 0, contrib.x);
    atomicAdd(o + 1, contrib.y);
    atomicAdd(o + 2, contrib.z);
    atomicAdd(o + 3, contrib.w);
#endif
}

// ---------------- utility kernels ----------------
__global__ void zero_kernel(int id, int n)
{
    float* p = bufptr(id);
    for (int i = blockIdx.x * blockDim.x + threadIdx.x; i < n; i += gridDim.x * blockDim.x)
        p[i] = 0.f;
}

__global__ void stats_kernel(int id, int n, int ncols, int prerelu)
{
    const float* X = bufptr(id);
    int c = threadIdx.x;
    float s = 0.f, s2 = 0.f;
    for (int r = blockIdx.x; r < n; r += gridDim.x) {
        float v = X[(size_t)r * ncols + c];
        if (prerelu) v = fmaxf(v, 0.f);
        s += v; s2 += v * v;
    }
    atomicAdd(&g_sums[c], (double)s);
    atomicAdd(&g_sums[128 + c], (double)s2);
}

__global__ void bnfin_kernel(int n, const float* __restrict__ gamma, const float* __restrict__ beta)
{
    int c = threadIdx.x;
    double mean = g_sums[c] / (double)n;
    double var  = g_sums[128 + c] / (double)n - mean * mean;
    float mul = gamma[c] * rsqrtf((float)var + 1e-5f);
    g_bnp[c] = mul;
    g_bnp[128 + c] = beta[c] - (float)mean * mul;
}

__global__ void bn_kernel(int inid, int outid, int n, int ncols, int prerelu, int postrelu)
{
    const float* X = bufptr(inid);
    float* Y = bufptr(outid);
    size_t total = (size_t)n * ncols;
    for (size_t i = (size_t)blockIdx.x * blockDim.x + threadIdx.x; i < total;
         i += (size_t)gridDim.x * blockDim.x) {
        int c = (int)(i % ncols);
        float v = X[i];
        if (prerelu) v = fmaxf(v, 0.f);
        float y = v * g_bnp[c] + g_bnp[128 + c];
        if (postrelu) y = fmaxf(y, 0.f);
        Y[i] = y;
    }
}

// final: out[r] = z2[r,:] . W3 + b3   (warp per row)
__global__ void final_kernel(const float* __restrict__ W3, const float* __restrict__ b3,
                             float* __restrict__ out, int B)
{
    int r = (blockIdx.x * blockDim.x + threadIdx.x) >> 5;
    int lane = threadIdx.x & 31;
    if (r >= B) return;
    const float* z = g_z2 + (size_t)r * 64;
    float acc = z[lane] * W3[lane] + z[lane + 32] * W3[lane + 32];
    acc += __shfl_xor_sync(0xffffffffu, acc, 1);
    acc += __shfl_xor_sync(0xffffffffu, acc, 2);
    acc += __shfl_xor_sync(0xffffffffu, acc, 4);
    acc += __shfl_xor_sync(0xffffffffu, acc, 8);
    acc += __shfl_xor_sync(0xffffffffu, acc, 16);
    if (lane == 0) out[r] = acc + b3[0];
}

// ---------------- host launcher ----------------
extern "C" void kernel_launch(void* const* d_in, const int* in_sizes, int n_in,
                              void* d_out, int out_size)
{
    int off = (n_in >= 31) ? 1 : 0;   // batch_size scalar may or may not be materialized
    const float* x_all = (const float*)d_in[0];
    const int*   ids   = (const int*)d_in[1];
    const int*   esrc  = (const int*)d_in[2];
    const int*   edst  = (const int*)d_in[3];
    const float* dts   = (const float*)d_in[4];
    const float* basis = (const float*)d_in[5 + off];
    const float* phase = (const float*)d_in[6 + off];
    const float* Wp    = (const float*)d_in[7 + off];
    const float* bp    = (const float*)d_in[8 + off];
    const float* Wq    = (const float*)d_in[9 + off];
    const float* bq    = (const float*)d_in[10 + off];
    const float* Wk    = (const float*)d_in[11 + off];
    const float* bk    = (const float*)d_in[12 + off];
    const float* Wv    = (const float*)d_in[13 + off];
    const float* bv    = (const float*)d_in[14 + off];
    const float* We    = (const float*)d_in[15 + off];
    const float* Wsk   = (const float*)d_in[16 + off];
    const float* bsk   = (const float*)d_in[17 + off];
    const float* bng   = (const float*)d_in[18 + off];
    const float* bnb   = (const float*)d_in[19 + off];
    const float* W1    = (const float*)d_in[20 + off];
    const float* b1    = (const float*)d_in[21 + off];
    const float* g1    = (const float*)d_in[22 + off];
    const float* be1   = (const float*)d_in[23 + off];
    const float* W2    = (const float*)d_in[24 + off];
    const float* b2    = (const float*)d_in[25 + off];
    const float* g2    = (const float*)d_in[26 + off];
    const float* be2   = (const float*)d_in[27 + off];
    const float* W3    = (const float*)d_in[28 + off];
    const float* b3    = (const float*)d_in[29 + off];

    int N = in_sizes[1];
    int E = in_sizes[2] / LNUM;
    int B = out_size;

    int gN = (N + 127) / 128;
    int gB = (B + 127) / 128;

    const int EDGEA_SMEM = (TD * HID + 8 * 4 * TD) * (int)sizeof(float);  // 64000 B
    cudaFuncSetAttribute(edgeA_kernel, cudaFuncAttributeMaxDynamicSharedMemorySize, EDGEA_SMEM);

    // h = relu(x_all[ids] @ Wp + bp)
    gemm_tc<128><<<gN, 256>>>(x_all, -1, ids, N, IN_DIM, Wp, bp, ID_H, 1);

    for (int i = 0; i < LNUM; i++) {
        size_t wo = (size_t)i * HID * HID;
        gemm_tc<128><<<gN, 256>>>(nullptr, ID_H, nullptr, N, HID, Wq + wo, bq + i*HID, ID_Q, 0);
        gemm_tc<128><<<gN, 256>>>(nullptr, ID_H, nullptr, N, HID, Wk + wo, bk + i*HID, ID_K, 0);
        gemm_tc<128><<<gN, 256>>>(nullptr, ID_H, nullptr, N, HID, Wv + wo, bv + i*HID, ID_V, 0);
        gemm_tc<128><<<gN, 256>>>(nullptr, ID_H, nullptr, N, HID, Wsk + wo, bsk + i*HID, ID_OUT, 0);

        zero_kernel<<<256, 256>>>(ID_S, N * NH);
        edgeA_kernel<<<(E + 127) / 128, 256, EDGEA_SMEM>>>(
            esrc + (size_t)i * E, edst + (size_t)i * E, dts + (size_t)i * E,
            basis, phase, We + (size_t)i * TD * HID, E);
        edgeB_kernel<<<(E + 7) / 8, 256>>>(edst + (size_t)i * E, E);

        zero_kernel<<<4, 256>>>(ID_SUMS, 512);
        stats_kernel<<<512, HID>>>(ID_OUT, N, HID, 1);
        bnfin_kernel<<<1, HID>>>(N, bng + i*HID, bnb + i*HID);
        bn_kernel<<<2048, 256>>>(ID_OUT, ID_H, N, HID, 1, 0);
    }

    // MLP head on first B rows
    gemm_tc<128><<<gB, 256>>>(nullptr, ID_H, nullptr, B, HID, W1, b1, ID_Z1, 0);
    zero_kernel<<<4, 256>>>(ID_SUMS, 512);
    stats_kernel<<<512, 128>>>(ID_Z1, B, 128, 0);
    bnfin_kernel<<<1, 128>>>(B, g1, be1);
    bn_kernel<<<1024, 256>>>(ID_Z1, ID_Z1, B, 128, 0, 1);

    gemm_tc<64><<<gB, 256>>>(nullptr, ID_Z1, nullptr, B, HID, W2, b2, ID_Z2, 0);
    zero_kernel<<<4, 256>>>(ID_SUMS, 512);
    stats_kernel<<<512, 64>>>(ID_Z2, B, 64, 0);
    bnfin_kernel<<<1, 64>>>(B, g2, be2);
    bn_kernel<<<1024, 256>>>(ID_Z2, ID_Z2, B, 64, 0, 1);

    final_kernel<<<(B * 32 + 255) / 256, 256>>>(W3, b3, (float*)d_out, B);
}

// round 5
// speedup vs baseline: 1.3796x; 1.2333x over previous
#include <cuda_runtime.h>
#include <cuda_bf16.h>
#include <math.h>
#include <stdint.h>

#define LNUM 2
#define IN_DIM 172
#define HID 128
#define NH 4
#define HD 32
#define TD 100
#define NMAX 150016
#define EMAX 500224
#define BMAX 16384

#define ID_Q    1
#define ID_K    2
#define ID_V    3
#define ID_OUT  4
#define ID_Z1   5
#define ID_Z2   6
#define ID_S    7
#define ID_SUMS 8
#define ID_HH   9
#define ID_HL   10
#define ID_Z1H  11
#define ID_Z1L  12

// ---------------- scratch (static device memory; no cudaMalloc allowed) ----------------
__device__ float  g_q  [(size_t)NMAX * HID];
__device__ float  g_k  [(size_t)NMAX * HID];
__device__ float  g_v  [(size_t)NMAX * HID];
__device__ float  g_out[(size_t)NMAX * HID];
__device__ float  g_e  [(size_t)EMAX * HID];   // holds v[src] + e  per edge
__device__ float  g_a  [(size_t)EMAX * NH];
__device__ float  g_s  [(size_t)NMAX * NH];
__device__ float  g_z1 [(size_t)BMAX * HID];
__device__ float  g_z2 [(size_t)BMAX * (HID/2)];
__device__ __nv_bfloat16 g_hh [(size_t)NMAX * HID];
__device__ __nv_bfloat16 g_hl [(size_t)NMAX * HID];
__device__ __nv_bfloat16 g_z1h[(size_t)BMAX * HID];
__device__ __nv_bfloat16 g_z1l[(size_t)BMAX * HID];
__device__ double g_sums[256];   // [0:128) col sums, [128:256) col sumsq
__device__ float  g_bnp[256];    // [0:128) mul, [128:256) add

__device__ __forceinline__ float* bufptr(int id) {
    switch (id) {
        case ID_Q:    return g_q;
        case ID_K:    return g_k;
        case ID_V:    return g_v;
        case ID_OUT:  return g_out;
        case ID_Z1:   return g_z1;
        case ID_Z2:   return g_z2;
        case ID_S:    return g_s;
        case ID_SUMS: return (float*)g_sums;
    }
    return nullptr;
}

__device__ __forceinline__ __nv_bfloat16* bufptr16(int id) {
    switch (id) {
        case ID_HH:  return g_hh;
        case ID_HL:  return g_hl;
        case ID_Z1H: return g_z1h;
        case ID_Z1L: return g_z1l;
    }
    return nullptr;
}

// ---------------- bf16 hi/lo split helpers ----------------
__device__ __forceinline__ void bsplit(float x, float y, uint32_t& hi, uint32_t& lo) {
    __nv_bfloat162 h;
    h.x = __float2bfloat16_rn(x);
    h.y = __float2bfloat16_rn(y);
    hi = *reinterpret_cast<uint32_t*>(&h);
    __nv_bfloat162 l;
    l.x = __float2bfloat16_rn(x - __bfloat162float(h.x));
    l.y = __float2bfloat16_rn(y - __bfloat162float(h.y));
    lo = *reinterpret_cast<uint32_t*>(&l);
}

__device__ __forceinline__ void mma_bf16(float* c, const uint32_t* a, const uint32_t* b) {
    asm volatile(
        "mma.sync.aligned.m16n8k16.row.col.f32.bf16.bf16.f32 "
        "{%0,%1,%2,%3}, {%4,%5,%6,%7}, {%8,%9}, {%0,%1,%2,%3};\n"
        : "+f"(c[0]), "+f"(c[1]), "+f"(c[2]), "+f"(c[3])
        : "r"(a[0]), "r"(a[1]), "r"(a[2]), "r"(a[3]), "r"(b[0]), "r"(b[1]));
}

// ---------------- tensor-core GEMM: C[M,NC] = A[M,K] @ W[K,NC] + bias ----------------
// bf16 hi/lo split, 3 MMA products (hh + lh + hl) => ~fp32 accuracy.
// PRESPLIT: A comes from pre-split bf16 hi/lo arrays (AhId/AlId); else fp32 (+gather), split in-kernel.
// Optional split outputs ChId/ClId (bf16 hi/lo of post-bias/relu result).
template <int NC, bool PRESPLIT>
__global__ void __launch_bounds__(256, 2)
gemm_tc(const float* __restrict__ Aext, int AhId, int AlId, const int* __restrict__ gather,
        int M, int K, const float* __restrict__ W, const float* __restrict__ bias,
        int Cid, int relu, int ChId, int ClId)
{
    constexpr int BM = 128, BK = 32, K2 = 16;
    constexpr int AP = 20;        // uint32 columns per A smem row (16 + 4 pad) -> conflict-free
    constexpr int WP = NC + 8;    // W smem row pad -> conflict-free
    constexpr int WN = NC / 2;    // per-warp n extent (64 or 32)
    constexpr int NT = WN / 8;    // 8 or 4
    constexpr int MT = 2;

    __shared__ uint32_t Ah[BM][AP], Al[BM][AP];   // packed bf16 pairs along k
    __shared__ uint32_t Wh[K2][WP], Wl[K2][WP];

    const int tid  = threadIdx.x;
    const int warp = tid >> 5, lane = tid & 31;
    const int wm = warp >> 1, wn = warp & 1;      // 4 x 2 warp grid
    const int lr = lane >> 2, lc = lane & 3;
    const int row0 = blockIdx.x * BM;

    float acc[MT][NT][4];
    #pragma unroll
    for (int mt = 0; mt < MT; mt++)
        #pragma unroll
        for (int nt = 0; nt < NT; nt++)
            #pragma unroll
            for (int j = 0; j < 4; j++) acc[mt][nt][j] = 0.f;

    for (int k0 = 0; k0 < K; k0 += BK) {
        if (PRESPLIT) {
            // A from bf16 hi/lo arrays: raw uint4 copies (8 bf16 each)
            const __nv_bfloat16* AH = bufptr16(AhId);
            const __nv_bfloat16* AL = bufptr16(AlId);
            #pragma unroll
            for (int i = 0; i < 4; i++) {
                int task = tid + i * 256;     // 1024 = 2 arrays * 128 rows * 4 uint4
                int arr = task >> 9;
                int r   = (task >> 2) & 127;
                int u   = task & 3;
                int grow = row0 + r;
                uint4 val = make_uint4(0u, 0u, 0u, 0u);
                const __nv_bfloat16* base = arr ? AL : AH;
                if (grow < M)
                    val = *(const uint4*)(base + (size_t)grow * K + k0 + u * 8);
                *(uint4*)&((arr ? Al : Ah)[r][u * 4]) = val;
            }
        } else {
            #pragma unroll
            for (int i = 0; i < 4; i++) {
                int task = tid + i * 256;     // 1024 tasks = 128 rows x 8 float4-groups
                int r  = task >> 3;
                int kg = task & 7;
                int k  = k0 + kg * 4;
                float4 v = make_float4(0.f, 0.f, 0.f, 0.f);
                int grow = row0 + r;
                if (grow < M) {
                    long long ar = gather ? (long long)gather[grow] : (long long)grow;
                    const float* ap = Aext + ar * K + k;
                    if (k + 4 <= K) v = *(const float4*)ap;
                    else {
                        if (k     < K) v.x = ap[0];
                        if (k + 1 < K) v.y = ap[1];
                        if (k + 2 < K) v.z = ap[2];
                        if (k + 3 < K) v.w = ap[3];
                    }
                }
                uint32_t h0, l0, h1, l1;
                bsplit(v.x, v.y, h0, l0);
                bsplit(v.z, v.w, h1, l1);
                *(uint2*)&Ah[r][kg * 2] = make_uint2(h0, h1);
                *(uint2*)&Al[r][kg * 2] = make_uint2(l0, l1);
            }
        }
        // ---- fill W tile (coalesced float4 reads, split, uint4 stores) ----
        #pragma unroll
        for (int i = 0; i < (K2 * NC / 4) / 256; i++) {
            int task = tid + i * 256;       // K2 x NC/4 tasks
            int kk = task / (NC / 4);
            int n  = (task % (NC / 4)) * 4;
            int k  = k0 + kk * 2;
            float4 r0 = make_float4(0.f,0.f,0.f,0.f), r1 = make_float4(0.f,0.f,0.f,0.f);
            if (k     < K) r0 = *(const float4*)(W + (size_t)k * NC + n);
            if (k + 1 < K) r1 = *(const float4*)(W + (size_t)(k + 1) * NC + n);
            uint4 vh, vl;
            bsplit(r0.x, r1.x, vh.x, vl.x);
            bsplit(r0.y, r1.y, vh.y, vl.y);
            bsplit(r0.z, r1.z, vh.z, vl.z);
            bsplit(r0.w, r1.w, vh.w, vl.w);
            *(uint4*)&Wh[kk][n] = vh;
            *(uint4*)&Wl[kk][n] = vl;
        }
        __syncthreads();

        #pragma unroll
        for (int ks = 0; ks < 2; ks++) {
            const int kb = ks * 8;
            uint32_t ah[MT][4], al[MT][4];
            #pragma unroll
            for (int mt = 0; mt < MT; mt++) {
                int m = wm * 32 + mt * 16 + lr;
                ah[mt][0] = Ah[m    ][kb + lc];
                ah[mt][1] = Ah[m + 8][kb + lc];
                ah[mt][2] = Ah[m    ][kb + lc + 4];
                ah[mt][3] = Ah[m + 8][kb + lc + 4];
                al[mt][0] = Al[m    ][kb + lc];
                al[mt][1] = Al[m + 8][kb + lc];
                al[mt][2] = Al[m    ][kb + lc + 4];
                al[mt][3] = Al[m + 8][kb + lc + 4];
            }
            #pragma unroll
            for (int nt = 0; nt < NT; nt++) {
                int n = wn * WN + nt * 8 + lr;
                uint32_t bh[2], bl[2];
                bh[0] = Wh[kb + lc    ][n];
                bh[1] = Wh[kb + lc + 4][n];
                bl[0] = Wl[kb + lc    ][n];
                bl[1] = Wl[kb + lc + 4][n];
                #pragma unroll
                for (int mt = 0; mt < MT; mt++) {
                    mma_bf16(acc[mt][nt], ah[mt], bh);
                    mma_bf16(acc[mt][nt], al[mt], bh);
                    mma_bf16(acc[mt][nt], ah[mt], bl);
                }
            }
        }
        __syncthreads();
    }

    // ---- epilogue: bias (+relu), fp32 and/or bf16-split stores ----
    float* C = (Cid >= 0) ? bufptr(Cid) : nullptr;
    __nv_bfloat16* CH = (ChId >= 0) ? bufptr16(ChId) : nullptr;
    __nv_bfloat16* CL = (ChId >= 0) ? bufptr16(ClId) : nullptr;
    #pragma unroll
    for (int mt = 0; mt < MT; mt++) {
        int rA = row0 + wm * 32 + mt * 16 + lr;
        #pragma unroll
        for (int nt = 0; nt < NT; nt++) {
            int col = wn * WN + nt * 8 + lc * 2;
            float b0 = bias[col], b1 = bias[col + 1];
            float2 v0 = make_float2(acc[mt][nt][0] + b0, acc[mt][nt][1] + b1);
            float2 v1 = make_float2(acc[mt][nt][2] + b0, acc[mt][nt][3] + b1);
            if (relu) {
                v0.x = fmaxf(v0.x, 0.f); v0.y = fmaxf(v0.y, 0.f);
                v1.x = fmaxf(v1.x, 0.f); v1.y = fmaxf(v1.y, 0.f);
            }
            #pragma unroll
            for (int half = 0; half < 2; half++) {
                int r = rA + half * 8;
                if (r >= M) continue;
                float2 v = half ? v1 : v0;
                size_t idx = (size_t)r * NC + col;
                if (C) *(float2*)&C[idx] = v;
                if (CH) {
                    __nv_bfloat16 h0 = __float2bfloat16_rn(v.x);
                    __nv_bfloat16 h1 = __float2bfloat16_rn(v.y);
                    CH[idx]     = h0;
                    CH[idx + 1] = h1;
                    CL[idx]     = __float2bfloat16_rn(v.x - __bfloat162float(h0));
                    CL[idx + 1] = __float2bfloat16_rn(v.y - __bfloat162float(h1));
                }
            }
        }
    }
}

// ---------------- edge pass A ----------------
// te = cos(dt*f+p); e = te@We; alpha = q[dst].(k[src]+e)/sqrt(HD); a=exp(alpha);
// s[dst] += a; g_e[e] = v[src] + e   (pre-adding v so pass B needs no src gather)
__global__ void edgeA_kernel(const int* __restrict__ src, const int* __restrict__ dst,
                             const float* __restrict__ dt,
                             const float* __restrict__ freq, const float* __restrict__ ph,
                             const float* __restrict__ We, int E)
{
    extern __shared__ float sh[];
    float* Wes = sh;                 // TD*HID
    float* tes = sh + TD * HID;      // 8 warps * 4 edges * TD (interleaved [t*4+j])

    for (int idx = threadIdx.x; idx < TD * HID; idx += blockDim.x) Wes[idx] = We[idx];
    __syncthreads();

    int warp = threadIdx.x >> 5, lane = threadIdx.x & 31;
    float* myte = tes + warp * (4 * TD);
    const float4* W4 = (const float4*)Wes;
    const float inv_sqrt_d = 0.1767766952966369f;

    long long base = (long long)blockIdx.x * 128 + warp * 16;

    for (int it = 0; it < 4; it++) {
        long long e0 = base + it * 4;
        float d[4];
        #pragma unroll
        for (int j = 0; j < 4; j++) {
            long long e = e0 + j;
            d[j] = (e < E) ? dt[e] : 0.f;
        }
        for (int t = lane; t < TD; t += 32) {
            float f = freq[t], p = ph[t];
            float4 tv;
            tv.x = cosf(fmaf(d[0], f, p));
            tv.y = cosf(fmaf(d[1], f, p));
            tv.z = cosf(fmaf(d[2], f, p));
            tv.w = cosf(fmaf(d[3], f, p));
            ((float4*)myte)[t] = tv;
        }
        __syncwarp();

        float4 accs[4];
        #pragma unroll
        for (int j = 0; j < 4; j++) { accs[j].x=0.f; accs[j].y=0.f; accs[j].z=0.f; accs[j].w=0.f; }

        #pragma unroll 4
        for (int t = 0; t < TD; t++) {
            float4 tv = ((const float4*)myte)[t];
            float4 w  = W4[t * 32 + lane];
            accs[0].x += tv.x*w.x; accs[0].y += tv.x*w.y; accs[0].z += tv.x*w.z; accs[0].w += tv.x*w.w;
            accs[1].x += tv.y*w.x; accs[1].y += tv.y*w.y; accs[1].z += tv.y*w.z; accs[1].w += tv.y*w.w;
            accs[2].x += tv.z*w.x; accs[2].y += tv.z*w.y; accs[2].z += tv.z*w.z; accs[2].w += tv.z*w.w;
            accs[3].x += tv.w*w.x; accs[3].y += tv.w*w.y; accs[3].z += tv.w*w.z; accs[3].w += tv.w*w.w;
        }

        #pragma unroll
        for (int j = 0; j < 4; j++) {
            long long e = e0 + j;
            if (e >= E) continue;
            float4 ev = accs[j];
            int sI = src[e], dI = dst[e];
            float4 kv = ((const float4*)g_k)[(size_t)sI * 32 + lane];
            float4 qv = ((const float4*)g_q)[(size_t)dI * 32 + lane];
            float4 vv = ((const float4*)g_v)[(size_t)sI * 32 + lane];
            float4 ve; ve.x = vv.x + ev.x; ve.y = vv.y + ev.y; ve.z = vv.z + ev.z; ve.w = vv.w + ev.w;
            ((float4*)g_e)[(size_t)e * 32 + lane] = ve;
            float p = qv.x*(kv.x+ev.x) + qv.y*(kv.y+ev.y) + qv.z*(kv.z+ev.z) + qv.w*(kv.w+ev.w);
            p += __shfl_xor_sync(0xffffffffu, p, 1);
            p += __shfl_xor_sync(0xffffffffu, p, 2);
            p += __shfl_xor_sync(0xffffffffu, p, 4);
            if ((lane & 7) == 0) {
                int head = lane >> 3;
                float a = expf(p * inv_sqrt_d);
                g_a[(size_t)e * NH + head] = a;
                atomicAdd(&g_s[(size_t)dI * NH + head], a);
            }
        }
        __syncwarp();
    }
}

// ---------------- edge pass B: out[dst] += (a/s[dst]) * g_e[e] ----------------
__global__ void edgeB_kernel(const int* __restrict__ dst, int E)
{
    long long e = (long long)blockIdx.x * 8 + (threadIdx.x >> 5);
    if (e >= E) return;
    int lane = threadIdx.x & 31;
    int dI = dst[e];
    int head = lane >> 3;
    float a = g_a[(size_t)e * NH + head];
    float ssum = g_s[(size_t)dI * NH + head];
    float w = a / (ssum + 1e-16f);
    float4 ve = ((const float4*)g_e)[(size_t)e * 32 + lane];
    float4 contrib;
    contrib.x = w * ve.x; contrib.y = w * ve.y; contrib.z = w * ve.z; contrib.w = w * ve.w;
    atomicAdd(((float4*)g_out) + (size_t)dI * 32 + lane, contrib);
}

// ---------------- utility kernels ----------------
__global__ void zero_kernel(int id, int n)
{
    float* p = bufptr(id);
    for (int i = blockIdx.x * blockDim.x + threadIdx.x; i < n; i += gridDim.x * blockDim.x)
        p[i] = 0.f;
}

__global__ void stats_kernel(int id, int n, int ncols, int prerelu)
{
    const float* X = bufptr(id);
    int c = threadIdx.x;
    float s = 0.f, s2 = 0.f;
    for (int r = blockIdx.x; r < n; r += gridDim.x) {
        float v = X[(size_t)r * ncols + c];
        if (prerelu) v = fmaxf(v, 0.f);
        s += v; s2 += v * v;
    }
    atomicAdd(&g_sums[c], (double)s);
    atomicAdd(&g_sums[128 + c], (double)s2);
}

__global__ void bnfin_kernel(int n, const float* __restrict__ gamma, const float* __restrict__ beta)
{
    int c = threadIdx.x;
    double mean = g_sums[c] / (double)n;
    double var  = g_sums[128 + c] / (double)n - mean * mean;
    float mul = gamma[c] * rsqrtf((float)var + 1e-5f);
    g_bnp[c] = mul;
    g_bnp[128 + c] = beta[c] - (float)mean * mul;
}

// BN apply: optional fp32 out, optional bf16 hi/lo split out.
__global__ void bn_kernel(int inid, int n, int ncols, int prerelu, int postrelu,
                          int outfId, int outhId, int outlId)
{
    const float* X = bufptr(inid);
    float* Yf = (outfId >= 0) ? bufptr(outfId) : nullptr;
    __nv_bfloat16* Yh = (outhId >= 0) ? bufptr16(outhId) : nullptr;
    __nv_bfloat16* Yl = (outhId >= 0) ? bufptr16(outlId) : nullptr;
    size_t total = (size_t)n * ncols;
    for (size_t i = (size_t)blockIdx.x * blockDim.x + threadIdx.x; i < total;
         i += (size_t)gridDim.x * blockDim.x) {
        int c = (int)(i % ncols);
        float v = X[i];
        if (prerelu) v = fmaxf(v, 0.f);
        float y = v * g_bnp[c] + g_bnp[128 + c];
        if (postrelu) y = fmaxf(y, 0.f);
        if (Yf) Yf[i] = y;
        if (Yh) {
            __nv_bfloat16 h = __float2bfloat16_rn(y);
            Yh[i] = h;
            Yl[i] = __float2bfloat16_rn(y - __bfloat162float(h));
        }
    }
}

// final: out[r] = z2[r,:] . W3 + b3   (warp per row)
__global__ void final_kernel(const float* __restrict__ W3, const float* __restrict__ b3,
                             float* __restrict__ out, int B)
{
    int r = (blockIdx.x * blockDim.x + threadIdx.x) >> 5;
    int lane = threadIdx.x & 31;
    if (r >= B) return;
    const float* z = g_z2 + (size_t)r * 64;
    float acc = z[lane] * W3[lane] + z[lane + 32] * W3[lane + 32];
    acc += __shfl_xor_sync(0xffffffffu, acc, 1);
    acc += __shfl_xor_sync(0xffffffffu, acc, 2);
    acc += __shfl_xor_sync(0xffffffffu, acc, 4);
    acc += __shfl_xor_sync(0xffffffffu, acc, 8);
    acc += __shfl_xor_sync(0xffffffffu, acc, 16);
    if (lane == 0) out[r] = acc + b3[0];
}

// ---------------- host launcher ----------------
extern "C" void kernel_launch(void* const* d_in, const int* in_sizes, int n_in,
                              void* d_out, int out_size)
{
    int off = (n_in >= 31) ? 1 : 0;   // batch_size scalar may or may not be materialized
    const float* x_all = (const float*)d_in[0];
    const int*   ids   = (const int*)d_in[1];
    const int*   esrc  = (const int*)d_in[2];
    const int*   edst  = (const int*)d_in[3];
    const float* dts   = (const float*)d_in[4];
    const float* basis = (const float*)d_in[5 + off];
    const float* phase = (const float*)d_in[6 + off];
    const float* Wp    = (const float*)d_in[7 + off];
    const float* bp    = (const float*)d_in[8 + off];
    const float* Wq    = (const float*)d_in[9 + off];
    const float* bq    = (const float*)d_in[10 + off];
    const float* Wk    = (const float*)d_in[11 + off];
    const float* bk    = (const float*)d_in[12 + off];
    const float* Wv    = (const float*)d_in[13 + off];
    const float* bv    = (const float*)d_in[14 + off];
    const float* We    = (const float*)d_in[15 + off];
    const float* Wsk   = (const float*)d_in[16 + off];
    const float* bsk   = (const float*)d_in[17 + off];
    const float* bng   = (const float*)d_in[18 + off];
    const float* bnb   = (const float*)d_in[19 + off];
    const float* W1    = (const float*)d_in[20 + off];
    const float* b1    = (const float*)d_in[21 + off];
    const float* g1    = (const float*)d_in[22 + off];
    const float* be1   = (const float*)d_in[23 + off];
    const float* W2    = (const float*)d_in[24 + off];
    const float* b2    = (const float*)d_in[25 + off];
    const float* g2    = (const float*)d_in[26 + off];
    const float* be2   = (const float*)d_in[27 + off];
    const float* W3    = (const float*)d_in[28 + off];
    const float* b3    = (const float*)d_in[29 + off];

    int N = in_sizes[1];
    int E = in_sizes[2] / LNUM;
    int B = out_size;

    int gN = (N + 127) / 128;
    int gB = (B + 127) / 128;

    const int EDGEA_SMEM = (TD * HID + 8 * 4 * TD) * (int)sizeof(float);  // 64000 B
    cudaFuncSetAttribute(edgeA_kernel, cudaFuncAttributeMaxDynamicSharedMemorySize, EDGEA_SMEM);

    // h = relu(x_all[ids] @ Wp + bp)  -> written directly as bf16 hi/lo split
    gemm_tc<128, false><<<gN, 256>>>(x_all, -1, -1, ids, N, IN_DIM, Wp, bp,
                                     -1, 1, ID_HH, ID_HL);

    for (int i = 0; i < LNUM; i++) {
        size_t wo = (size_t)i * HID * HID;
        gemm_tc<128, true><<<gN, 256>>>(nullptr, ID_HH, ID_HL, nullptr, N, HID,
                                        Wq + wo, bq + i*HID, ID_Q, 0, -1, -1);
        gemm_tc<128, true><<<gN, 256>>>(nullptr, ID_HH, ID_HL, nullptr, N, HID,
                                        Wk + wo, bk + i*HID, ID_K, 0, -1, -1);
        gemm_tc<128, true><<<gN, 256>>>(nullptr, ID_HH, ID_HL, nullptr, N, HID,
                                        Wv + wo, bv + i*HID, ID_V, 0, -1, -1);
        gemm_tc<128, true><<<gN, 256>>>(nullptr, ID_HH, ID_HL, nullptr, N, HID,
                                        Wsk + wo, bsk + i*HID, ID_OUT, 0, -1, -1);

        zero_kernel<<<256, 256>>>(ID_S, N * NH);
        edgeA_kernel<<<(E + 127) / 128, 256, EDGEA_SMEM>>>(
            esrc + (size_t)i * E, edst + (size_t)i * E, dts + (size_t)i * E,
            basis, phase, We + (size_t)i * TD * HID, E);
        edgeB_kernel<<<(E + 7) / 8, 256>>>(edst + (size_t)i * E, E);

        zero_kernel<<<4, 256>>>(ID_SUMS, 512);
        stats_kernel<<<512, HID>>>(ID_OUT, N, HID, 1);
        bnfin_kernel<<<1, HID>>>(N, bng + i*HID, bnb + i*HID);
        // h = bn(relu(out)) -> bf16 hi/lo split only (no fp32 consumer)
        bn_kernel<<<2048, 256>>>(ID_OUT, N, HID, 1, 0, -1, ID_HH, ID_HL);
    }

    // MLP head on first B rows
    gemm_tc<128, true><<<gB, 256>>>(nullptr, ID_HH, ID_HL, nullptr, B, HID,
                                    W1, b1, ID_Z1, 0, -1, -1);
    zero_kernel<<<4, 256>>>(ID_SUMS, 512);
    stats_kernel<<<512, 128>>>(ID_Z1, B, 128, 0);
    bnfin_kernel<<<1, 128>>>(B, g1, be1);
    bn_kernel<<<1024, 256>>>(ID_Z1, B, 128, 0, 1, -1, ID_Z1H, ID_Z1L);

    gemm_tc<64, true><<<gB, 256>>>(nullptr, ID_Z1H, ID_Z1L, nullptr, B, HID,
                                   W2, b2, ID_Z2, 0, -1, -1);
    zero_kernel<<<4, 256>>>(ID_SUMS, 512);
    stats_kernel<<<512, 64>>>(ID_Z2, B, 64, 0);
    bnfin_kernel<<<1, 64>>>(B, g2, be2);
    bn_kernel<<<1024, 256>>>(ID_Z2, B, 64, 0, 1, ID_Z2, -1, -1);

    final_kernel<<<(B * 32 + 255) / 256, 256>>>(W3, b3, (float*)d_out, B);
}